// round 15
// baseline (speedup 1.0000x reference)
#include <cuda_runtime.h>

#define NPOS 1296
#define GRID1D 36
#define PP 7
#define NP 10
#define WINS 20
#define LL 14
#define HH 160
#define WW 160
#define PLANES 32
#define STEPS (NPOS*NP)   // 12960

// ---------------- scratch (static device globals; no runtime allocation) ----
__device__ float    g_M[49*49];              // Wp @ Wb
__device__ float    g_v[NP*49];              // (bp + pos_emb[n]) @ Wb + bb
__device__ float    g_den[(size_t)PLANES*STEPS*49]; // ~81 MB
__device__ unsigned g_rowsU[(size_t)PLANES*NPOS*3]; // row0 bytes, 4/u32, pad=200
__device__ unsigned g_colsU[(size_t)PLANES*NPOS*3]; // col0 bytes

// ---------------- f32x2 helpers ----------------------------------------------
__device__ __forceinline__ unsigned long long pk2(float lo, float hi) {
    unsigned long long r;
    asm("mov.b64 %0, {%1, %2};" : "=l"(r) : "f"(lo), "f"(hi));
    return r;
}
__device__ __forceinline__ void fma2(unsigned long long& acc, unsigned long long a,
                                     unsigned long long b) {
    asm("fma.rn.f32x2 %0, %1, %2, %3;" : "=l"(acc) : "l"(a), "l"(b), "l"(acc));
}
__device__ __forceinline__ void upk2(unsigned long long v, float& lo, float& hi) {
    asm("mov.b64 {%0, %1}, %2;" : "=f"(lo), "=f"(hi) : "l"(v));
}

// ---------------- K-1: dummy (keeps ncu capture slot on k_fold) --------------
__global__ void k_dummy() {}

// ---------------- K0: fuse the two projections (block per output row) --------
__global__ __launch_bounds__(64) void k_precompute(const float* __restrict__ Wp,
                                                   const float* __restrict__ bp,
                                                   const float* __restrict__ pe,
                                                   const float* __restrict__ Wb,
                                                   const float* __restrict__ bb) {
    const int row = blockIdx.x;   // 0..48 -> M rows, 49..58 -> v rows
    const int t = threadIdx.x;
    __shared__ float sRow[128];
    if (row < 49) {
        for (int e = t; e < 128; e += 64) sRow[e] = Wp[row*128 + e];
    } else {
        const int n = row - 49;
        for (int e = t; e < 128; e += 64) sRow[e] = bp[e] + pe[n*128 + e];
    }
    __syncthreads();
    for (int q = t; q < 49; q += 64) {
        float acc = (row < 49) ? 0.f : bb[q];
        #pragma unroll 8
        for (int e = 0; e < 128; e++) acc += sRow[e] * Wb[e*49 + q];
        if (row < 49) g_M[row*49 + q] = acc;
        else          g_v[(row-49)*49 + q] = acc;
    }
}

// ---------------- K1: warp-per-(pos,plane) stage1 ----------------------------
__global__ __launch_bounds__(256) void k_stage1(const float* __restrict__ images) {
    const int warp = threadIdx.x >> 5;
    const int lane = threadIdx.x & 31;
    const int pos   = blockIdx.x * 8 + warp;
    const int plane = blockIdx.y;

    const int ixp = pos / GRID1D;      // x outer
    const int iyp = pos % GRID1D;      // y inner
    const int x = ixp * 4, y = iyp * 4;
    const int xb0 = max(x - 7, 0), yb0 = max(y - 7, 0);
    const int winW = min(x + 13, WW) - xb0;
    const int winH = min(y + 13, HH) - yb0;
    const int rx = x - xb0, ry = y - yb0;   // ref offset inside window

    __shared__ float sWinAll[8][400];
    __shared__ __align__(16) float sPTAll[8][588];   // 49 x 12 padded
    __shared__ int   sIdsAll[8][10];
    __shared__ int   sOffAll[8][10];
    float* sWin = sWinAll[warp];
    float* sPT  = sPTAll[warp];
    int*   sIds = sIdsAll[warp];
    int*   sOff = sOffAll[warp];

    const float* img = images + (size_t)plane * (HH*WW);
    #pragma unroll
    for (int o = lane; o < 400; o += 32)
        sWin[o] = img[(yb0 + o/20)*WW + xb0 + o%20];
    __syncwarp();

    // sliding-window conv: lane -> (row i, half), 7 contiguous outputs each
    const int i  = min(lane >> 1, 13);     // 0..13
    const int hf = lane & 1;               // 0/1
    const int j0 = hf * 7;                 // 0 or 7
    float acc[7];
    #pragma unroll
    for (int m = 0; m < 7; m++) acc[m] = 0.f;
    #pragma unroll
    for (int dy = 0; dy < 7; dy++) {
        float w[13];
        const int rb = (i + dy)*20 + j0;
        #pragma unroll
        for (int c = 0; c < 13; c++) w[c] = sWin[rb + c];
        #pragma unroll
        for (int dx = 0; dx < 7; dx++) {
            const float rv = sWin[(ry + dy)*20 + rx + dx];
            #pragma unroll
            for (int m = 0; m < 7; m++)
                acc[m] += w[m + dx] * rv;
        }
    }

    // unique ordering keys; o = i*14 + j0 + m
    const float NEG_INF = -__int_as_float(0x7f800000);
    unsigned long long keys[7];
    #pragma unroll
    for (int m = 0; m < 7; m++) {
        const int j = j0 + m;
        const int o = i*14 + j;
        const float sim = (i <= winH - 7 && j <= winW - 7) ? acc[m] : NEG_INF;
        const unsigned b = __float_as_uint(sim);
        const unsigned ord = (b & 0x80000000u) ? ~b : (b | 0x80000000u);
        keys[m] = (lane < 28) ? (((unsigned long long)ord << 32) | (unsigned)(65535 - o))
                              : 0ull;
    }

    // exact top-10: 10 rounds of warp max-extraction (keys unique)
    int ids[10];
    #pragma unroll
    for (int r = 0; r < 10; r++) {
        unsigned long long best = keys[0];
        #pragma unroll
        for (int m = 1; m < 7; m++) if (keys[m] > best) best = keys[m];
        #pragma unroll
        for (int s = 16; s; s >>= 1) {
            const unsigned long long o2 = __shfl_xor_sync(0xffffffffu, best, s);
            if (o2 > best) best = o2;
        }
        const int id = 65535 - (int)(best & 0xffffu);
        ids[r] = id;
        const int bi = id / 14, bj = id % 14;
        const int ownLane = (bi << 1) | (bj >= 7);
        if (lane == ownLane) {
            const int mw = bj - ((bj >= 7) ? 7 : 0);
            #pragma unroll
            for (int mm = 0; mm < 7; mm++) if (mm == mw) keys[mm] = 0ull;
        }
    }
    if (lane == 0) {
        #pragma unroll
        for (int n = 0; n < 10; n++) {
            sIds[n] = ids[n];
            sOff[n] = (ids[n] / 14) * 20 + (ids[n] % 14);
        }
    }
    __syncwarp();

    // extract transposed patches: sPT[k*12+n] = win[oy+k%7][ox+k/7]
    for (int e = lane; e < 490; e += 32) {
        const int k = e / 10, n = e - k*10;
        sPT[k*12 + n] = sWin[sOff[n] + (k % 7)*20 + (k / 7)];
    }
    // coord words (source bug preserved: row0 = col-offset + yb0, col0 = row-offset + xb0)
    if (lane < 6) {
        const int w = lane;
        const int widx = (w < 3) ? w : w - 3;
        unsigned v = 0;
        #pragma unroll
        for (int p = 0; p < 4; p++) {
            const int nn = widx*4 + p;
            unsigned byte = 200;
            if (nn < 10) {
                const int id = sIds[nn];
                byte = (w < 3) ? (unsigned)(id % 14 + yb0)    // row0
                               : (unsigned)(id / 14 + xb0);   // col0
            }
            v |= byte << (p * 8);
        }
        unsigned* dst = (w < 3) ? g_rowsU : g_colsU;
        dst[((size_t)plane*NPOS + pos)*3 + widx] = v;
    }
    __syncwarp();

    // den[n][q] = sum_k patchT[k][n] * M[k][q] + v[n][q]
    // f32x2 packed FMA; patch pairs read directly as 64-bit lanes of LDS.128
    {
        const int q1 = lane;
        const int q2 = lane + 32;
        const bool has2 = (q2 < 49);
        unsigned long long accA[5], accB[5];
        #pragma unroll
        for (int j = 0; j < 5; j++) { accA[j] = 0ull; accB[j] = 0ull; }
        const ulonglong2* U2 = (const ulonglong2*)sPT;
        #pragma unroll 7
        for (int k = 0; k < 49; k++) {
            const float m1 = __ldg(&g_M[k*49 + q1]);
            const float m2 = has2 ? __ldg(&g_M[k*49 + q2]) : 0.f;
            const unsigned long long m1p = pk2(m1, m1);
            const unsigned long long m2p = pk2(m2, m2);
            const ulonglong2 A = U2[k*3 + 0];
            const ulonglong2 B = U2[k*3 + 1];
            const ulonglong2 C = U2[k*3 + 2];
            fma2(accA[0], m1p, A.x); fma2(accA[1], m1p, A.y);
            fma2(accA[2], m1p, B.x); fma2(accA[3], m1p, B.y);
            fma2(accA[4], m1p, C.x);
            fma2(accB[0], m2p, A.x); fma2(accB[1], m2p, A.y);
            fma2(accB[2], m2p, B.x); fma2(accB[3], m2p, B.y);
            fma2(accB[4], m2p, C.x);
        }
        float a[10], b2[10];
        #pragma unroll
        for (int j = 0; j < 5; j++) {
            upk2(accA[j], a[2*j], a[2*j+1]);
            upk2(accB[j], b2[2*j], b2[2*j+1]);
        }
        float* denOut = g_den + ((size_t)plane * STEPS + (size_t)pos * NP) * 49;
        #pragma unroll
        for (int n = 0; n < 10; n++) {
            denOut[n*49 + q1] = a[n] + __ldg(&g_v[n*49 + q1]);
            if (has2) denOut[n*49 + q2] = b2[n] + __ldg(&g_v[n*49 + q2]);
        }
    }
}

// ---------------- K2: warp-coherent candidate fold ----------------------------
__device__ __forceinline__ int flo(int c) { return (c <= 19) ? 0 : ((c - 9) >> 2); }
__device__ __forceinline__ int fhi(int c) { return min(GRID1D - 1, (c + 7) >> 2); }
__device__ __forceinline__ unsigned pack4(unsigned hm) {
    return ((hm & 0x01010101u) * 0x01020408u) >> 24;   // byte flags -> 4 bits
}
__device__ __forceinline__ unsigned mask10t(unsigned vrep, const unsigned* p,
                                            unsigned thr) {
    unsigned m0 = __vcmpltu4(__vsub4(vrep, p[0]), thr);
    unsigned m1 = __vcmpltu4(__vsub4(vrep, p[1]), thr);
    unsigned m2 = __vcmpltu4(__vsub4(vrep, p[2]), thr);
    return pack4(m0) | (pack4(m1) << 4) | (pack4(m2) << 8);
}

__global__ __launch_bounds__(256) void k_fold(const float* __restrict__ images,
                                              float* __restrict__ out) {
    const int plane = blockIdx.y;
    const int tile  = blockIdx.x;               // 0..99
    const int TR = (tile / 10) * 16, TC = (tile % 10) * 16;
    const int t = threadIdx.x;
    const int warp = t >> 5;
    const int r  = TR + (t >> 4);
    const int cc = TC + (t & 15);

    const int Rlo = flo(TR), Rhi = fhi(TR + 15);
    const int Clo = flo(TC), Chi = fhi(TC + 15);
    const int rW = Rhi - Rlo + 1;               // <= 10
    const int cW = Chi - Clo + 1;               // <= 10
    const int nCell = rW * cW;

    __shared__ unsigned sImR[100*3], sImC[100*3];   // im layout: (ix-Clo)*rW + iy-Rlo
    __shared__ unsigned sCnR[100*3], sCnC[100*3];   // cnt layout: (ix-Rlo)*cW + iy-Clo
    __shared__ unsigned short tRvR[100*16];         // (TR+i) vs im rows
    __shared__ unsigned short tRvC[100*16];         // (TR+i) vs cnt cols
    __shared__ unsigned short cuCvC[100];           // col-union vs im cols
    __shared__ unsigned short cuCvR[100];           // col-union vs cnt rows
    __shared__ unsigned short sRCim[100*10];        // row0 | col0<<8, im layout
    __shared__ unsigned short sRCcn[100*10];        // row0 | col0<<8, cnt layout
    __shared__ int sBaseIm[100*10];                 // step*49 - row0*7 - col0
    __shared__ float sRecip[96];

    for (int s = t; s < nCell*3; s += 256) {
        const int slot = s / 3, w = s - slot*3;
        const int ixo = slot / rW, iyo = slot - ixo*rW;
        const size_t g = ((size_t)plane*NPOS + (Clo + ixo)*GRID1D + (Rlo + iyo))*3 + w;
        sImR[s] = g_rowsU[g]; sImC[s] = g_colsU[g];
        const int ixo2 = slot / cW, iyo2 = slot - ixo2*cW;
        const size_t g2 = ((size_t)plane*NPOS + (Rlo + ixo2)*GRID1D + (Clo + iyo2))*3 + w;
        sCnR[s] = g_rowsU[g2]; sCnC[s] = g_colsU[g2];
    }
    if (t < 96) sRecip[t] = t ? (1.0f / (float)t) : 0.f;
    __syncthreads();

    const unsigned SEVEN = 0x07070707u;
    const unsigned T22   = 0x16161616u;
    for (int e = t; e < nCell*16; e += 256) {
        const int slot = e >> 4, i = e & 15;
        const unsigned rv = (unsigned)(TR + i) * 0x01010101u;
        tRvR[e] = (unsigned short)mask10t(rv, &sImR[slot*3], SEVEN);
        tRvC[e] = (unsigned short)mask10t(rv, &sCnC[slot*3], SEVEN);
    }
    {
        const unsigned cu = (unsigned)(TC + 15) * 0x01010101u;
        for (int s2 = t; s2 < nCell; s2 += 256) {
            cuCvC[s2] = (unsigned short)mask10t(cu, &sImC[s2*3], T22);
            cuCvR[s2] = (unsigned short)mask10t(cu, &sCnR[s2*3], T22);
        }
    }
    for (int e = t; e < nCell*10; e += 256) {
        const int slot = e / 10, n = e - slot*10;
        const int sh = (n & 3) * 8;
        const int rIm = (sImR[slot*3 + (n >> 2)] >> sh) & 0xff;
        const int cIm = (sImC[slot*3 + (n >> 2)] >> sh) & 0xff;
        sRCim[e] = (unsigned short)(rIm | (cIm << 8));
        const int rCn = (sCnR[slot*3 + (n >> 2)] >> sh) & 0xff;
        const int cCn = (sCnC[slot*3 + (n >> 2)] >> sh) & 0xff;
        sRCcn[e] = (unsigned short)(rCn | (cCn << 8));
        const int ixo = slot / rW, iyo = slot - ixo*rW;
        const int step = (((Clo + ixo)*GRID1D) + (Rlo + iyo))*NP + n;
        sBaseIm[e] = step*49 - rIm*7 - cIm;
    }
    __syncthreads();

    float val = images[(size_t)plane * (HH*WW) + r * WW + cc];

    // warp-uniform ranges: A = block col range, B = warp row-pair range
    const int r0 = TR + 2*warp;
    const int wRlo = flo(r0), wRhi = fhi(r0 + 1);
    const int rp0 = 2*warp;
    const int pixOff = r*7 + cc;
    const float* den = g_den + (size_t)plane * STEPS * 49;

    if (wRlo <= wRhi) {
        int pcnt = 1;
        const int xlo = min(Clo, wRlo), xhi = max(Chi, wRhi);
        const int xgap = max(Clo, wRlo);
        for (int ix = xlo; ix <= xhi; ix++) {
            const bool inA = (ix >= Clo) & (ix <= Chi);     // im x-valid
            const bool inB = (ix >= wRlo) & (ix <= wRhi);   // cnt x-valid
            if (!inA && !inB) { ix = xgap - 1; continue; }
            int ylo, yhi, ygap;
            if (inA && inB) { ylo = xlo; yhi = xhi; ygap = xgap; }
            else if (inA)   { ylo = wRlo; yhi = wRhi; ygap = ylo; }
            else            { ylo = Clo;  yhi = Chi;  ygap = ylo; }
            const int imRow = (ix - Clo) * rW;
            const int cnRow = (ix - Rlo) * cW;
            for (int iy = ylo; iy <= yhi; iy++) {
                const bool qIm = inA & (iy >= wRlo) & (iy <= wRhi);
                const bool qCn = inB & (iy >= Clo) & (iy <= Chi);
                if (!qIm && !qCn) { iy = ygap - 1; continue; }
                const int imSlot = imRow + iy - Rlo;
                const int cnSlot = cnRow + iy - Clo;
                unsigned uIm = 0, uCn = 0;
                if (qIm)
                    uIm = ((unsigned)tRvR[imSlot*16 + rp0] |
                           (unsigned)tRvR[imSlot*16 + rp0 + 1]) & (unsigned)cuCvC[imSlot];
                if (qCn)
                    uCn = ((unsigned)tRvC[cnSlot*16 + rp0] |
                           (unsigned)tRvC[cnSlot*16 + rp0 + 1]) & (unsigned)cuCvR[cnSlot];
                unsigned mm = uIm | uCn;
                if (!mm) continue;
                const unsigned short* rcTab = qIm ? &sRCim[imSlot*10] : &sRCcn[cnSlot*10];
                const int baseOff = qIm ? imSlot*10 : 0;   // safe dummy when !qIm
                do {
                    const int n = __ffs(mm) - 1; mm &= mm - 1;
                    const unsigned rc = rcTab[n];
                    const int row0 = rc & 0xff, col0 = rc >> 8;
                    const bool imHit = ((unsigned)(r - row0) < 7u) &
                                       ((unsigned)(cc - col0) < 7u);
                    const bool cnHit = ((unsigned)(r - col0) < 7u) &
                                       ((unsigned)(cc - row0) < 7u);
                    if (imHit) {
                        const float d = __ldg(den + sBaseIm[baseOff + n] + pixOff);
                        val = (val * (float)pcnt + d) * sRecip[pcnt + 1];
                    }
                    pcnt += cnHit;
                } while (mm);
            }
        }
    }
    out[(size_t)plane * (HH*WW) + r * WW + cc] = val;
}

// ---------------- launch ------------------------------------------------------
extern "C" void kernel_launch(void* const* d_in, const int* in_sizes, int n_in,
                              void* d_out, int out_size) {
    const float* images = (const float*)d_in[0];
    const float* Wp     = (const float*)d_in[1];
    const float* bp     = (const float*)d_in[2];
    const float* pe     = (const float*)d_in[3];
    const float* Wb     = (const float*)d_in[4];
    const float* bb     = (const float*)d_in[5];
    float* out = (float*)d_out;
    (void)in_sizes; (void)n_in; (void)out_size;

    k_dummy<<<1, 32>>>();

    k_precompute<<<59, 64>>>(Wp, bp, pe, Wb, bb);

    dim3 g1(162, PLANES);
    k_stage1<<<g1, 256>>>(images);

    dim3 g2(100, PLANES);
    k_fold<<<g2, 256>>>(images, out);
}

// round 16
// speedup vs baseline: 1.4988x; 1.4988x over previous
#include <cuda_runtime.h>

#define NPOS 1296
#define GRID1D 36
#define PP 7
#define NP 10
#define WINS 20
#define LL 14
#define HH 160
#define WW 160
#define PLANES 32
#define STEPS (NPOS*NP)   // 12960

// ---------------- scratch (static device globals; no runtime allocation) ----
__device__ float    g_M[49*49];              // Wp @ Wb
__device__ float    g_v[NP*49];              // (bp + pos_emb[n]) @ Wb + bb
__device__ float    g_den[(size_t)PLANES*STEPS*49]; // ~81 MB
__device__ unsigned g_rowsU[(size_t)PLANES*NPOS*3]; // row0 bytes, 4/u32, pad=200
__device__ unsigned g_colsU[(size_t)PLANES*NPOS*3]; // col0 bytes

// ---------------- f32x2 helpers ----------------------------------------------
__device__ __forceinline__ unsigned long long pk2(float lo, float hi) {
    unsigned long long r;
    asm("mov.b64 %0, {%1, %2};" : "=l"(r) : "f"(lo), "f"(hi));
    return r;
}
__device__ __forceinline__ void fma2(unsigned long long& acc, unsigned long long a,
                                     unsigned long long b) {
    asm("fma.rn.f32x2 %0, %1, %2, %3;" : "=l"(acc) : "l"(a), "l"(b), "l"(acc));
}
__device__ __forceinline__ void upk2(unsigned long long v, float& lo, float& hi) {
    asm("mov.b64 {%0, %1}, %2;" : "=f"(lo), "=f"(hi) : "l"(v));
}

// ---------------- K-1: dummy (keeps ncu capture slot on k_fold) --------------
__global__ void k_dummy() {}

// ---------------- K0: fuse the two projections (block per output row) --------
__global__ __launch_bounds__(64) void k_precompute(const float* __restrict__ Wp,
                                                   const float* __restrict__ bp,
                                                   const float* __restrict__ pe,
                                                   const float* __restrict__ Wb,
                                                   const float* __restrict__ bb) {
    const int row = blockIdx.x;   // 0..48 -> M rows, 49..58 -> v rows
    const int t = threadIdx.x;
    __shared__ float sRow[128];
    if (row < 49) {
        for (int e = t; e < 128; e += 64) sRow[e] = Wp[row*128 + e];
    } else {
        const int n = row - 49;
        for (int e = t; e < 128; e += 64) sRow[e] = bp[e] + pe[n*128 + e];
    }
    __syncthreads();
    for (int q = t; q < 49; q += 64) {
        float acc = (row < 49) ? 0.f : bb[q];
        #pragma unroll 8
        for (int e = 0; e < 128; e++) acc += sRow[e] * Wb[e*49 + q];
        if (row < 49) g_M[row*49 + q] = acc;
        else          g_v[(row-49)*49 + q] = acc;
    }
}

// ---------------- K1: warp-per-(pos,plane) stage1 ----------------------------
__global__ __launch_bounds__(256) void k_stage1(const float* __restrict__ images) {
    const int warp = threadIdx.x >> 5;
    const int lane = threadIdx.x & 31;
    const int pos   = blockIdx.x * 8 + warp;
    const int plane = blockIdx.y;

    const int ixp = pos / GRID1D;      // x outer
    const int iyp = pos % GRID1D;      // y inner
    const int x = ixp * 4, y = iyp * 4;
    const int xb0 = max(x - 7, 0), yb0 = max(y - 7, 0);
    const int winW = min(x + 13, WW) - xb0;
    const int winH = min(y + 13, HH) - yb0;
    const int rx = x - xb0, ry = y - yb0;   // ref offset inside window

    __shared__ float sWinAll[8][400];
    __shared__ __align__(16) float sPTAll[8][588];   // 49 x 12 padded
    __shared__ int   sIdsAll[8][10];
    __shared__ int   sOffAll[8][10];
    float* sWin = sWinAll[warp];
    float* sPT  = sPTAll[warp];
    int*   sIds = sIdsAll[warp];
    int*   sOff = sOffAll[warp];

    const float* img = images + (size_t)plane * (HH*WW);
    #pragma unroll
    for (int o = lane; o < 400; o += 32)
        sWin[o] = img[(yb0 + o/20)*WW + xb0 + o%20];
    __syncwarp();

    // sliding-window conv: lane -> (row i, half), 7 contiguous outputs each
    const int i  = min(lane >> 1, 13);     // 0..13
    const int hf = lane & 1;               // 0/1
    const int j0 = hf * 7;                 // 0 or 7
    float acc[7];
    #pragma unroll
    for (int m = 0; m < 7; m++) acc[m] = 0.f;
    #pragma unroll
    for (int dy = 0; dy < 7; dy++) {
        float w[13];
        const int rb = (i + dy)*20 + j0;
        #pragma unroll
        for (int c = 0; c < 13; c++) w[c] = sWin[rb + c];
        #pragma unroll
        for (int dx = 0; dx < 7; dx++) {
            const float rv = sWin[(ry + dy)*20 + rx + dx];
            #pragma unroll
            for (int m = 0; m < 7; m++)
                acc[m] += w[m + dx] * rv;
        }
    }

    // unique ordering keys; o = i*14 + j0 + m
    const float NEG_INF = -__int_as_float(0x7f800000);
    unsigned long long keys[7];
    #pragma unroll
    for (int m = 0; m < 7; m++) {
        const int j = j0 + m;
        const int o = i*14 + j;
        const float sim = (i <= winH - 7 && j <= winW - 7) ? acc[m] : NEG_INF;
        const unsigned b = __float_as_uint(sim);
        const unsigned ord = (b & 0x80000000u) ? ~b : (b | 0x80000000u);
        keys[m] = (lane < 28) ? (((unsigned long long)ord << 32) | (unsigned)(65535 - o))
                              : 0ull;
    }

    // exact top-10: 10 rounds of warp max-extraction (keys unique)
    int ids[10];
    #pragma unroll
    for (int r = 0; r < 10; r++) {
        unsigned long long best = keys[0];
        #pragma unroll
        for (int m = 1; m < 7; m++) if (keys[m] > best) best = keys[m];
        #pragma unroll
        for (int s = 16; s; s >>= 1) {
            const unsigned long long o2 = __shfl_xor_sync(0xffffffffu, best, s);
            if (o2 > best) best = o2;
        }
        const int id = 65535 - (int)(best & 0xffffu);
        ids[r] = id;
        const int bi = id / 14, bj = id % 14;
        const int ownLane = (bi << 1) | (bj >= 7);
        if (lane == ownLane) {
            const int mw = bj - ((bj >= 7) ? 7 : 0);
            #pragma unroll
            for (int mm = 0; mm < 7; mm++) if (mm == mw) keys[mm] = 0ull;
        }
    }
    if (lane == 0) {
        #pragma unroll
        for (int n = 0; n < 10; n++) {
            sIds[n] = ids[n];
            sOff[n] = (ids[n] / 14) * 20 + (ids[n] % 14);
        }
    }
    __syncwarp();

    // extract transposed patches: sPT[k*12+n] = win[oy+k%7][ox+k/7]
    for (int e = lane; e < 490; e += 32) {
        const int k = e / 10, n = e - k*10;
        sPT[k*12 + n] = sWin[sOff[n] + (k % 7)*20 + (k / 7)];
    }
    // coord words (source bug preserved: row0 = col-offset + yb0, col0 = row-offset + xb0)
    if (lane < 6) {
        const int w = lane;
        const int widx = (w < 3) ? w : w - 3;
        unsigned v = 0;
        #pragma unroll
        for (int p = 0; p < 4; p++) {
            const int nn = widx*4 + p;
            unsigned byte = 200;
            if (nn < 10) {
                const int id = sIds[nn];
                byte = (w < 3) ? (unsigned)(id % 14 + yb0)    // row0
                               : (unsigned)(id / 14 + xb0);   // col0
            }
            v |= byte << (p * 8);
        }
        unsigned* dst = (w < 3) ? g_rowsU : g_colsU;
        dst[((size_t)plane*NPOS + pos)*3 + widx] = v;
    }
    __syncwarp();

    // den[n][q] = sum_k patchT[k][n] * M[k][q] + v[n][q]
    // f32x2 packed FMA; patch pairs read directly as 64-bit lanes of LDS.128
    {
        const int q1 = lane;
        const int q2 = lane + 32;
        const bool has2 = (q2 < 49);
        unsigned long long accA[5], accB[5];
        #pragma unroll
        for (int j = 0; j < 5; j++) { accA[j] = 0ull; accB[j] = 0ull; }
        const ulonglong2* U2 = (const ulonglong2*)sPT;
        #pragma unroll 7
        for (int k = 0; k < 49; k++) {
            const float m1 = __ldg(&g_M[k*49 + q1]);
            const float m2 = has2 ? __ldg(&g_M[k*49 + q2]) : 0.f;
            const unsigned long long m1p = pk2(m1, m1);
            const unsigned long long m2p = pk2(m2, m2);
            const ulonglong2 A = U2[k*3 + 0];
            const ulonglong2 B = U2[k*3 + 1];
            const ulonglong2 C = U2[k*3 + 2];
            fma2(accA[0], m1p, A.x); fma2(accA[1], m1p, A.y);
            fma2(accA[2], m1p, B.x); fma2(accA[3], m1p, B.y);
            fma2(accA[4], m1p, C.x);
            fma2(accB[0], m2p, A.x); fma2(accB[1], m2p, A.y);
            fma2(accB[2], m2p, B.x); fma2(accB[3], m2p, B.y);
            fma2(accB[4], m2p, C.x);
        }
        float a[10], b2[10];
        #pragma unroll
        for (int j = 0; j < 5; j++) {
            upk2(accA[j], a[2*j], a[2*j+1]);
            upk2(accB[j], b2[2*j], b2[2*j+1]);
        }
        float* denOut = g_den + ((size_t)plane * STEPS + (size_t)pos * NP) * 49;
        #pragma unroll
        for (int n = 0; n < 10; n++) {
            denOut[n*49 + q1] = a[n] + __ldg(&g_v[n*49 + q1]);
            if (has2) denOut[n*49 + q2] = b2[n] + __ldg(&g_v[n*49 + q2]);
        }
    }
}

// ---------------- K2: role-split mask-table fold (R13) + warp-uniform branch -
__device__ __forceinline__ int flo(int c) { return (c <= 19) ? 0 : ((c - 9) >> 2); }
__device__ __forceinline__ int fhi(int c) { return min(GRID1D - 1, (c + 7) >> 2); }
__device__ __forceinline__ unsigned pack4(unsigned hm) {
    return ((hm & 0x01010101u) * 0x01020408u) >> 24;   // byte flags -> 4 bits
}
__device__ __forceinline__ unsigned mask10(unsigned vrep, const unsigned* p) {
    const unsigned seven = 0x07070707u;
    unsigned m0 = __vcmpltu4(__vsub4(vrep, p[0]), seven);
    unsigned m1 = __vcmpltu4(__vsub4(vrep, p[1]), seven);
    unsigned m2 = __vcmpltu4(__vsub4(vrep, p[2]), seven);
    return pack4(m0) | (pack4(m1) << 4) | (pack4(m2) << 8);
}

__global__ __launch_bounds__(256) void k_fold(const float* __restrict__ images,
                                              float* __restrict__ out) {
    const int plane = blockIdx.y;
    const int tile  = blockIdx.x;               // 0..99
    const int TR = (tile / 10) * 16, TC = (tile % 10) * 16;
    const int t = threadIdx.x;
    const int r  = TR + (t >> 4);
    const int cc = TC + (t & 15);

    const int Rlo = flo(TR), Rhi = fhi(TR + 15);
    const int Clo = flo(TC), Chi = fhi(TC + 15);
    const int rW = Rhi - Rlo + 1;               // <= 10
    const int cW = Chi - Clo + 1;               // <= 10
    const int nCell = rW * cW;                  // im and cnt rects have same count

    __shared__ unsigned sImR[100*3], sImC[100*3];   // im cells: ix-Clo major, iy-Rlo minor
    __shared__ unsigned sCnR[100*3], sCnC[100*3];   // cnt cells: ix-Rlo major, iy-Clo minor
    __shared__ unsigned short tRvR[100*16], tCvC[100*16]; // im masks
    __shared__ unsigned short tRvC[100*16], tCvR[100*16]; // cnt masks
    __shared__ int sBaseIm[100*10];   // den index base: step*49 - row0*7 - col0
    __shared__ float sRecip[96];

    for (int s = t; s < nCell*3; s += 256) {
        const int slot = s / 3, w = s - slot*3;
        const int ixo = slot / rW, iyo = slot - ixo*rW;
        const size_t g = ((size_t)plane*NPOS + (Clo + ixo)*GRID1D + (Rlo + iyo))*3 + w;
        sImR[s] = g_rowsU[g]; sImC[s] = g_colsU[g];
        const int ixo2 = slot / cW, iyo2 = slot - ixo2*cW;
        const size_t g2 = ((size_t)plane*NPOS + (Rlo + ixo2)*GRID1D + (Clo + iyo2))*3 + w;
        sCnR[s] = g_rowsU[g2]; sCnC[s] = g_colsU[g2];
    }
    if (t < 96) sRecip[t] = t ? (1.0f / (float)t) : 0.f;
    __syncthreads();

    for (int e = t; e < nCell*16; e += 256) {
        const int slot = e >> 4, i = e & 15;
        const unsigned rv = (unsigned)(TR + i) * 0x01010101u;
        const unsigned cv = (unsigned)(TC + i) * 0x01010101u;
        tRvR[e] = (unsigned short)mask10(rv, &sImR[slot*3]);
        tCvC[e] = (unsigned short)mask10(cv, &sImC[slot*3]);
        tRvC[e] = (unsigned short)mask10(rv, &sCnC[slot*3]);
        tCvR[e] = (unsigned short)mask10(cv, &sCnR[slot*3]);
    }
    // den base per (im cell, candidate): step*49 - row0*7 - col0
    for (int e = t; e < nCell*10; e += 256) {
        const int slot = e / 10, n = e - slot*10;
        const int ixo = slot / rW, iyo = slot - ixo*rW;
        const int step = (((Clo + ixo)*GRID1D) + (Rlo + iyo))*NP + n;
        const int row0 = (sImR[slot*3 + (n >> 2)] >> ((n & 3)*8)) & 0xff;
        const int col0 = (sImC[slot*3 + (n >> 2)] >> ((n & 3)*8)) & 0xff;
        sBaseIm[e] = step*49 - row0*7 - col0;
    }
    __syncthreads();

    float val = images[(size_t)plane * (HH*WW) + r * WW + cc];

    // im role: ix in f(cc), iy in f(r).  cnt role: ix in f(r), iy in f(cc).
    const int imXLo = flo(cc), imXHi = fhi(cc);
    const int cnXLo = flo(r),  cnXHi = fhi(r);
    const int rp = r - TR, cp = cc - TC;
    const int pixOff = r*7 + cc;
    const float* den = g_den + (size_t)plane * STEPS * 49;

    const bool activeRanges = (imXLo <= imXHi) && (cnXLo <= cnXHi);
    const bool disjoint = (cnXHi < imXLo) || (imXHi < cnXLo);
    const bool needOverlap = activeRanges && !disjoint;

    if (__any_sync(0xffffffffu, needOverlap)) {
        // ---- overlap path, warp-uniform choice (correct for ALL lanes) ----
        int pcnt = 1;
        const int xF = min(imXLo, cnXLo), xL = max(imXHi, cnXHi);
        for (int ix = xF; ix <= xL; ix++) {
            const bool okIm = (ix >= imXLo) & (ix <= imXHi);
            const bool okCn = (ix >= cnXLo) & (ix <= cnXHi);
            const int imRow = (ix - Clo) * rW;
            const int cnRow = (ix - Rlo) * cW;
            for (int iy = xF; iy <= xL; iy++) {
                const bool hIm = okIm & (iy >= cnXLo) & (iy <= cnXHi);
                const bool hCn = okCn & (iy >= imXLo) & (iy <= imXHi);
                if (!hIm && !hCn) continue;
                unsigned maskIm = 0, maskCn = 0;
                int imSlot = 0;
                if (hIm) {
                    imSlot = imRow + iy - Rlo;
                    maskIm = (unsigned)tRvR[imSlot*16 + rp] &
                             (unsigned)tCvC[imSlot*16 + cp];
                }
                if (hCn) {
                    const int cnSlot = cnRow + iy - Clo;
                    maskCn = (unsigned)tRvC[cnSlot*16 + rp] &
                             (unsigned)tCvR[cnSlot*16 + cp];
                }
                while (maskIm) {
                    const int n = __ffs(maskIm) - 1; maskIm &= maskIm - 1;
                    const int cntNow = pcnt + __popc(maskCn & ((1u << n) - 1u));
                    const float d = __ldg(den + sBaseIm[imSlot*10 + n] + pixOff);
                    val = (val * (float)cntNow + d) * sRecip[cntNow + 1];
                }
                pcnt += __popc(maskCn);
            }
        }
    } else if (activeRanges) {
        // ---- disjoint ranges: constant count for every im hit ----
        const bool cntFirst = (cnXHi < imXLo);
        int tot = 0;
        if (cntFirst) {
            for (int ix = cnXLo; ix <= cnXHi; ix++) {
                const int base = (ix - Rlo) * cW;
                #pragma unroll 3
                for (int iy = imXLo; iy <= imXHi; iy++) {
                    const int slot = base + iy - Clo;
                    tot += __popc((unsigned)tRvC[slot*16 + rp] &
                                  (unsigned)tCvR[slot*16 + cp]);
                }
            }
        }
        const int c = 1 + tot;
        const float G = sRecip[c + 1];
        const float F = (float)c * G;
        for (int ix = imXLo; ix <= imXHi; ix++) {
            const int imRow = (ix - Clo) * rW;
            #pragma unroll 3
            for (int iy = cnXLo; iy <= cnXHi; iy++) {
                const int slot = imRow + iy - Rlo;
                unsigned m = (unsigned)tRvR[slot*16 + rp] &
                             (unsigned)tCvC[slot*16 + cp];
                while (m) {
                    const int n = __ffs(m) - 1; m &= m - 1;
                    const float d = __ldg(den + sBaseIm[slot*10 + n] + pixOff);
                    val = val * F + d * G;
                }
            }
        }
    }
    out[(size_t)plane * (HH*WW) + r * WW + cc] = val;
}

// ---------------- launch ------------------------------------------------------
extern "C" void kernel_launch(void* const* d_in, const int* in_sizes, int n_in,
                              void* d_out, int out_size) {
    const float* images = (const float*)d_in[0];
    const float* Wp     = (const float*)d_in[1];
    const float* bp     = (const float*)d_in[2];
    const float* pe     = (const float*)d_in[3];
    const float* Wb     = (const float*)d_in[4];
    const float* bb     = (const float*)d_in[5];
    float* out = (float*)d_out;
    (void)in_sizes; (void)n_in; (void)out_size;

    k_dummy<<<1, 32>>>();

    k_precompute<<<59, 64>>>(Wp, bp, pe, Wb, bb);

    dim3 g1(162, PLANES);
    k_stage1<<<g1, 256>>>(images);

    dim3 g2(100, PLANES);
    k_fold<<<g2, 256>>>(images, out);
}